// round 7
// baseline (speedup 1.0000x reference)
#include <cuda_runtime.h>
#include <cuda_bf16.h>

#define DIM 128
#define NVOX (DIM * DIM * DIM)

// Work list for solidifying voxels: {idx (bit-cast), rot1.x, rot1.y, rot1.z}
__device__ int    g_count;
__device__ float4 g_list[NVOX];

__global__ void reset_kernel() { g_count = 0; }

// ---------------------------------------------------------------------------
// Pass 1: pure streaming — state/field/euler defaults + compaction of
// solidifying voxels. No neighbor gather here.
// ---------------------------------------------------------------------------
__global__ void __launch_bounds__(256) pass1_kernel(
    const float* __restrict__ x,     // [NVOX, 5]
    const float* __restrict__ out,   // [NVOX, 8]
    float* __restrict__ y)           // [NVOX, 5]
{
    int idx = blockIdx.x * blockDim.x + threadIdx.x;
    if (idx >= NVOX) return;

    const float* xp = x + (size_t)idx * 5;
    float s0f = __ldg(xp + 0);
    float e0x = __ldg(xp + 1), e0y = __ldg(xp + 2), e0z = __ldg(xp + 3);
    int state0 = (int)s0f;

    const float4* op = reinterpret_cast<const float4*>(out + (size_t)idx * 8);
    float4 o0 = __ldg(op + 0);   // logits
    float4 o1 = __ldg(op + 1);   // rot1(3), field

    // argmax over 4 logits, first-occurrence on ties (strict >)
    int amax = 0;
    float mv = o0.x;
    if (o0.y > mv) { mv = o0.y; amax = 1; }
    if (o0.z > mv) { mv = o0.z; amax = 2; }
    if (o0.w > mv) { mv = o0.w; amax = 3; }

    int state1 = (state0 == 0) ? 0 : amax;

    // field1 masking
    float field1 = o1.w;
    if (state1 <= 1) {
        field1 = -1.0f;
    } else if (state1 == 2) {
        field1 = fminf(fmaxf(field1, 0.0f), 0.92f);
    } else {  // state1 == 3
        field1 = 1.0f;
    }

    // euler1 default (pass 2 overwrites for solidifying voxels)
    float ex = e0x, ey = e0y, ez = e0z;
    if (state1 <= 1) { ex = -1.0f; ey = -1.0f; ez = -1.0f; }

    // compact solidifying voxels (warp-aggregated atomic)
    if (state0 <= 1 && state1 > 1) {
        int pos = atomicAdd(&g_count, 1);
        g_list[pos] = make_float4(__int_as_float(idx), o1.x, o1.y, o1.z);
    }

    float* yp = y + (size_t)idx * 5;
    yp[0] = (float)state1;
    yp[1] = ex;
    yp[2] = ey;
    yp[3] = ez;
    yp[4] = field1;
}

// ---------------------------------------------------------------------------
// Pass 2: dense 26-neighbor argmin over the compacted list (full-warp lanes).
// ---------------------------------------------------------------------------
__global__ void __launch_bounds__(256) pass2_kernel(
    const float* __restrict__ x,     // [NVOX, 5]
    float* __restrict__ y)           // [NVOX, 5]
{
    int n = g_count;
    int stride = gridDim.x * blockDim.x;
    for (int t = blockIdx.x * blockDim.x + threadIdx.x; t < n; t += stride) {
        float4 e = g_list[t];
        int idx = __float_as_int(e.x);
        float rx = e.y, ry = e.z, rz = e.w;

        int k = idx & (DIM - 1);
        int j = (idx >> 7) & (DIM - 1);
        int i = idx >> 14;

        // 26-neighbor argmin, zero-padded OOB, first-occurrence via strict <
        float best = 3.402823e38f;
        float cx = 0.0f, cy = 0.0f, cz = 0.0f;
        #pragma unroll
        for (int di = -1; di <= 1; di++) {
            #pragma unroll
            for (int dj = -1; dj <= 1; dj++) {
                #pragma unroll
                for (int dk = -1; dk <= 1; dk++) {
                    if (di == 0 && dj == 0 && dk == 0) continue;
                    int ni = i + di, nj = j + dj, nk = k + dk;
                    float nx = 0.0f, ny = 0.0f, nz = 0.0f;
                    if ((unsigned)ni < DIM && (unsigned)nj < DIM && (unsigned)nk < DIM) {
                        const float* np =
                            x + (size_t)((ni << 14) | (nj << 7) | nk) * 5;
                        nx = __ldg(np + 1); ny = __ldg(np + 2); nz = __ldg(np + 3);
                    }
                    float dx = nx - rx, dy = ny - ry, dz = nz - rz;
                    float d2 = dx * dx + dy * dy + dz * dz;
                    if (d2 < best) { best = d2; cx = nx; cy = ny; cz = nz; }
                }
            }
        }

        float* yp = y + (size_t)idx * 5;
        yp[1] = cx;
        yp[2] = cy;
        yp[3] = cz;
    }
}

extern "C" void kernel_launch(void* const* d_in, const int* in_sizes, int n_in,
                              void* d_out, int out_size)
{
    const float* x   = (const float*)d_in[0];   // NVOX*5 elements
    const float* out = (const float*)d_in[1];   // NVOX*8 elements
    float* y = (float*)d_out;                   // NVOX*5 elements

    reset_kernel<<<1, 1>>>();

    const int threads = 256;
    pass1_kernel<<<NVOX / threads, threads>>>(x, out, y);

    // Expected ~12.5% of NVOX solidifying; grid-stride covers any count.
    pass2_kernel<<<2048, threads>>>(x, y);
}